// round 1
// baseline (speedup 1.0000x reference)
#include <cuda_runtime.h>
#include <math.h>

#define NT    16384
#define DIMV  768
#define HIDV  3072
#define NE    5
#define BM    128
#define BN    128
#define BK    16
#define MAXROWS (2*NT + NE*BM)   /* 33408 */

/* ---- scratch (static device memory; allocation-free kernel_launch) ---- */
__device__ int   g_counts[NE];
__device__ int   g_fill[NE];
__device__ int   g_offsets[NE];
__device__ int   g_padded[NE];
__device__ int   g_tok_e[NT*2];
__device__ float g_tok_g[NT*2];
__device__ int   g_tok_row[NT*2];
__device__ int   g_row_token[MAXROWS];
__device__ float g_H[MAXROWS*HIDV];   /* ~410 MB */
__device__ float g_Y[MAXROWS*DIMV];   /* ~103 MB */

/* ---------------- setup kernels ---------------- */

__global__ void zero_kernel() {
    if (threadIdx.x < NE) { g_counts[threadIdx.x] = 0; g_fill[threadIdx.x] = 0; }
}

/* one warp per token: 5 logits, top-2, softmax over the two selected logits */
__global__ void gate_kernel(const float* __restrict__ x, const float* __restrict__ wg) {
    int t    = blockIdx.x * 4 + (threadIdx.x >> 5);
    int lane = threadIdx.x & 31;
    if (t >= NT) return;
    const float* xr = x + (size_t)t * DIMV;
    float a0=0.f,a1=0.f,a2=0.f,a3=0.f,a4=0.f;
    for (int i = lane; i < DIMV; i += 32) {
        float xv = xr[i];
        const float* wr = wg + i * NE;
        a0 += xv*wr[0]; a1 += xv*wr[1]; a2 += xv*wr[2]; a3 += xv*wr[3]; a4 += xv*wr[4];
    }
    #pragma unroll
    for (int o = 16; o; o >>= 1) {
        a0 += __shfl_xor_sync(0xffffffffu, a0, o);
        a1 += __shfl_xor_sync(0xffffffffu, a1, o);
        a2 += __shfl_xor_sync(0xffffffffu, a2, o);
        a3 += __shfl_xor_sync(0xffffffffu, a3, o);
        a4 += __shfl_xor_sync(0xffffffffu, a4, o);
    }
    if (lane == 0) {
        float v[NE] = {a0,a1,a2,a3,a4};
        int e0 = 0; float b0 = v[0];
        #pragma unroll
        for (int e = 1; e < NE; e++) if (v[e] > b0) { b0 = v[e]; e0 = e; }
        int e1 = -1; float b1 = -INFINITY;
        #pragma unroll
        for (int e = 0; e < NE; e++) if (e != e0 && v[e] > b1) { b1 = v[e]; e1 = e; }
        /* softmax([b0,b1]) with b0 >= b1 */
        float ex  = expf(b1 - b0);
        float inv = 1.f / (1.f + ex);
        atomicAdd(&g_counts[e0], 1);
        atomicAdd(&g_counts[e1], 1);
        g_tok_e[2*t]   = e0;      g_tok_e[2*t+1] = e1;
        g_tok_g[2*t]   = inv;     g_tok_g[2*t+1] = ex * inv;
    }
}

__global__ void offsets_kernel() {
    if (threadIdx.x == 0) {
        int off = 0;
        for (int e = 0; e < NE; e++) {
            g_offsets[e] = off;
            int p = ((g_counts[e] + BM - 1) / BM) * BM;
            g_padded[e] = p;
            off += p;
        }
    }
}

__global__ void clear_rows_kernel() {
    int i = blockIdx.x * blockDim.x + threadIdx.x;
    if (i < MAXROWS) g_row_token[i] = -1;
}

__global__ void scatter_kernel() {
    int i = blockIdx.x * blockDim.x + threadIdx.x;
    if (i < 2*NT) {
        int e   = g_tok_e[i];
        int pos = atomicAdd(&g_fill[e], 1);
        int row = g_offsets[e] + pos;
        g_row_token[row] = i >> 1;
        g_tok_row[i]     = row;
    }
}

/* ---------------- GEMM 1: H = gelu(gather(x) @ W1[e] + b1[e]) ---------------- */
/* tile 128x128, K-tile 16, 256 threads, 8x8 per thread (split-64 layout)       */

#define AS_STRIDE 132  /* multiple of 4 for float4 reads, decorrelates store banks */

__global__ __launch_bounds__(256, 2)
void gemm1_kernel(const float* __restrict__ x,
                  const float* __restrict__ W1, const float* __restrict__ b1v) {
    int e  = blockIdx.y >> 7;
    int tj = blockIdx.y & 127;
    if (tj * BM >= g_padded[e]) return;
    int row0 = g_offsets[e] + tj * BM;
    int col0 = blockIdx.x * BN;

    __shared__ float As[BK][AS_STRIDE];
    __shared__ float Bs[BK][BN];
    __shared__ int   s_tok[BM];

    int tid = threadIdx.x;
    if (tid < BM) s_tok[tid] = g_row_token[row0 + tid];
    __syncthreads();

    const float* Bsrc = W1 + (size_t)e * DIMV * HIDV;

    float acc[8][8];
    #pragma unroll
    for (int i = 0; i < 8; i++)
        #pragma unroll
        for (int j = 0; j < 8; j++) acc[i][j] = 0.f;

    int ty = tid >> 4;   /* 0..15 row group  */
    int tx = tid & 15;   /* 0..15 col group  */

    for (int kt = 0; kt < DIMV / BK; kt++) {
        int k0 = kt * BK;
        /* A: 128 rows x 16 k. lane-consecutive rows -> conflict-free stores */
        #pragma unroll
        for (int j = 0; j < 2; j++) {
            int idx  = tid + j * 256;        /* 0..511 */
            int arow = idx & 127;
            int k4   = (idx >> 7) * 4;       /* 0,4,8,12 */
            float4 v = make_float4(0.f, 0.f, 0.f, 0.f);
            int tok = s_tok[arow];
            if (tok >= 0) v = *(const float4*)(x + (size_t)tok * DIMV + k0 + k4);
            As[k4+0][arow] = v.x; As[k4+1][arow] = v.y;
            As[k4+2][arow] = v.z; As[k4+3][arow] = v.w;
        }
        /* B: 16 rows x 128 cols, coalesced float4 */
        #pragma unroll
        for (int j = 0; j < 2; j++) {
            int idx  = tid + j * 256;
            int krow = idx >> 5;             /* 0..15 */
            int c4   = (idx & 31) * 4;
            *(float4*)&Bs[krow][c4] =
                *(const float4*)(Bsrc + (size_t)(k0 + krow) * HIDV + col0 + c4);
        }
        __syncthreads();
        #pragma unroll
        for (int k = 0; k < BK; k++) {
            float a[8], b[8];
            *(float4*)&a[0] = *(float4*)&As[k][ty*4];
            *(float4*)&a[4] = *(float4*)&As[k][ty*4 + 64];
            *(float4*)&b[0] = *(float4*)&Bs[k][tx*4];
            *(float4*)&b[4] = *(float4*)&Bs[k][tx*4 + 64];
            #pragma unroll
            for (int i = 0; i < 8; i++)
                #pragma unroll
                for (int j = 0; j < 8; j++) acc[i][j] += a[i] * b[j];
        }
        __syncthreads();
    }

    /* epilogue: bias + exact gelu, store gathered rows */
    #pragma unroll
    for (int i = 0; i < 8; i++) {
        int m = ty*4 + (i & 3) + ((i >= 4) ? 64 : 0);
        int tok = s_tok[m];
        if (tok < 0) continue;
        float* dst = g_H + (size_t)(row0 + m) * HIDV + col0;
        #pragma unroll
        for (int jh = 0; jh < 2; jh++) {
            float4 o;
            float* op = (float*)&o;
            #pragma unroll
            for (int jj = 0; jj < 4; jj++) {
                int j = jh*4 + jj;
                int n = tx*4 + jj + (jh ? 64 : 0);
                float c = acc[i][j] + b1v[e * HIDV + col0 + n];
                op[jj] = 0.5f * c * (1.f + erff(c * 0.70710678118654752f));
            }
            *(float4*)(dst + tx*4 + (jh ? 64 : 0)) = o;
        }
    }
}

/* ---------------- GEMM 2: Y = H @ W2[e] + b2[e] ---------------- */

__global__ __launch_bounds__(256, 2)
void gemm2_kernel(const float* __restrict__ W2, const float* __restrict__ b2v) {
    int e  = blockIdx.y >> 7;
    int tj = blockIdx.y & 127;
    if (tj * BM >= g_padded[e]) return;
    int row0 = g_offsets[e] + tj * BM;
    int col0 = blockIdx.x * BN;

    __shared__ float As[BK][AS_STRIDE];
    __shared__ float Bs[BK][BN];
    __shared__ int   s_tok[BM];

    int tid = threadIdx.x;
    if (tid < BM) s_tok[tid] = g_row_token[row0 + tid];
    __syncthreads();

    const float* Bsrc = W2 + (size_t)e * HIDV * DIMV;

    float acc[8][8];
    #pragma unroll
    for (int i = 0; i < 8; i++)
        #pragma unroll
        for (int j = 0; j < 8; j++) acc[i][j] = 0.f;

    int ty = tid >> 4;
    int tx = tid & 15;

    for (int kt = 0; kt < HIDV / BK; kt++) {
        int k0 = kt * BK;
        #pragma unroll
        for (int j = 0; j < 2; j++) {
            int idx  = tid + j * 256;
            int arow = idx & 127;
            int k4   = (idx >> 7) * 4;
            /* pad rows of g_H are never written -> stay 0 from bss init */
            float4 v = *(const float4*)(g_H + (size_t)(row0 + arow) * HIDV + k0 + k4);
            As[k4+0][arow] = v.x; As[k4+1][arow] = v.y;
            As[k4+2][arow] = v.z; As[k4+3][arow] = v.w;
        }
        #pragma unroll
        for (int j = 0; j < 2; j++) {
            int idx  = tid + j * 256;
            int krow = idx >> 5;
            int c4   = (idx & 31) * 4;
            *(float4*)&Bs[krow][c4] =
                *(const float4*)(Bsrc + (size_t)(k0 + krow) * DIMV + col0 + c4);
        }
        __syncthreads();
        #pragma unroll
        for (int k = 0; k < BK; k++) {
            float a[8], b[8];
            *(float4*)&a[0] = *(float4*)&As[k][ty*4];
            *(float4*)&a[4] = *(float4*)&As[k][ty*4 + 64];
            *(float4*)&b[0] = *(float4*)&Bs[k][tx*4];
            *(float4*)&b[4] = *(float4*)&Bs[k][tx*4 + 64];
            #pragma unroll
            for (int i = 0; i < 8; i++)
                #pragma unroll
                for (int j = 0; j < 8; j++) acc[i][j] += a[i] * b[j];
        }
        __syncthreads();
    }

    #pragma unroll
    for (int i = 0; i < 8; i++) {
        int m = ty*4 + (i & 3) + ((i >= 4) ? 64 : 0);
        int tok = s_tok[m];
        if (tok < 0) continue;
        float* dst = g_Y + (size_t)(row0 + m) * DIMV + col0;
        #pragma unroll
        for (int jh = 0; jh < 2; jh++) {
            float4 o;
            float* op = (float*)&o;
            #pragma unroll
            for (int jj = 0; jj < 4; jj++) {
                int j = jh*4 + jj;
                int n = tx*4 + jj + (jh ? 64 : 0);
                op[jj] = acc[i][j] + b2v[e * DIMV + col0 + n];
            }
            *(float4*)(dst + tx*4 + (jh ? 64 : 0)) = o;
        }
    }
}

/* ---------------- combine: out = log(g0*exp(y0) + g1*exp(y1)) ---------------- */

__global__ void combine_kernel(float* __restrict__ out) {
    int idx = blockIdx.x * blockDim.x + threadIdx.x;
    if (idx >= NT * DIMV) return;
    int t = idx / DIMV;
    int d = idx - t * DIMV;
    int   r0 = g_tok_row[2*t],   r1 = g_tok_row[2*t+1];
    float g0 = g_tok_g[2*t],     g1 = g_tok_g[2*t+1];
    float acc = g0 * expf(g_Y[(size_t)r0 * DIMV + d])
              + g1 * expf(g_Y[(size_t)r1 * DIMV + d]);
    out[idx] = logf(acc == 0.f ? 2.2204460492503131e-16f : acc);
}

/* ---------------- launch ---------------- */

extern "C" void kernel_launch(void* const* d_in, const int* in_sizes, int n_in,
                              void* d_out, int out_size) {
    (void)in_sizes; (void)n_in; (void)out_size;
    const float* x   = (const float*)d_in[0];
    const float* wg  = (const float*)d_in[1];
    const float* W1  = (const float*)d_in[2];
    const float* b1v = (const float*)d_in[3];
    const float* W2  = (const float*)d_in[4];
    const float* b2v = (const float*)d_in[5];
    float* out = (float*)d_out;

    zero_kernel<<<1, 32>>>();
    gate_kernel<<<NT/4, 128>>>(x, wg);
    offsets_kernel<<<1, 32>>>();
    clear_rows_kernel<<<(MAXROWS + 255)/256, 256>>>();
    scatter_kernel<<<(2*NT + 255)/256, 256>>>();

    dim3 g1(HIDV / BN, NE * (NT / BM));
    gemm1_kernel<<<g1, 256>>>(x, W1, b1v);

    dim3 g2(DIMV / BN, NE * (NT / BM));
    gemm2_kernel<<<g2, 256>>>(W2, b2v);

    combine_kernel<<<(NT*DIMV + 255)/256, 256>>>(out);
}

// round 2
// speedup vs baseline: 2.5588x; 2.5588x over previous
#include <cuda_runtime.h>
#include <math.h>
#include <stdint.h>

#define NT    16384
#define DIMV  768
#define HIDV  3072
#define NE    5
#define BM    128
#define BN    128
#define BK    32
#define MAXROWS (2*NT + NE*BM)   /* 33408 */

#define AS_STRIDE 36   /* floats per A smem row (32 + 4 pad) */
#define BS_STRIDE 132  /* floats per B smem row (128 + 4 pad) */
#define ABUF (BM*AS_STRIDE)        /* 4608 floats */
#define BBUF (BK*BS_STRIDE)        /* 4224 floats */
#define SMEM_FLOATS (2*ABUF + 2*BBUF + 128)
#define SMEM_BYTES  (SMEM_FLOATS*4)   /* 71168 */

/* ---- scratch ---- */
__device__ int   g_counts[NE];
__device__ int   g_fill[NE];
__device__ int   g_offsets[NE];
__device__ int   g_padded[NE];
__device__ int   g_tok_e[NT*2];
__device__ float g_tok_g[NT*2];
__device__ int   g_tok_row[NT*2];
__device__ int   g_row_token[MAXROWS];
__device__ float g_H[(size_t)MAXROWS*HIDV];   /* ~410 MB */
__device__ float g_Y[(size_t)MAXROWS*DIMV];   /* ~103 MB */

/* ---------------- setup kernels ---------------- */

__global__ void zero_kernel() {
    if (threadIdx.x < NE) { g_counts[threadIdx.x] = 0; g_fill[threadIdx.x] = 0; }
}

__global__ void gate_kernel(const float* __restrict__ x, const float* __restrict__ wg) {
    int t    = blockIdx.x * 4 + (threadIdx.x >> 5);
    int lane = threadIdx.x & 31;
    if (t >= NT) return;
    const float* xr = x + (size_t)t * DIMV;
    float a0=0.f,a1=0.f,a2=0.f,a3=0.f,a4=0.f;
    for (int i = lane; i < DIMV; i += 32) {
        float xv = xr[i];
        const float* wr = wg + i * NE;
        a0 += xv*wr[0]; a1 += xv*wr[1]; a2 += xv*wr[2]; a3 += xv*wr[3]; a4 += xv*wr[4];
    }
    #pragma unroll
    for (int o = 16; o; o >>= 1) {
        a0 += __shfl_xor_sync(0xffffffffu, a0, o);
        a1 += __shfl_xor_sync(0xffffffffu, a1, o);
        a2 += __shfl_xor_sync(0xffffffffu, a2, o);
        a3 += __shfl_xor_sync(0xffffffffu, a3, o);
        a4 += __shfl_xor_sync(0xffffffffu, a4, o);
    }
    if (lane == 0) {
        float v[NE] = {a0,a1,a2,a3,a4};
        int e0 = 0; float b0 = v[0];
        #pragma unroll
        for (int e = 1; e < NE; e++) if (v[e] > b0) { b0 = v[e]; e0 = e; }
        int e1 = -1; float b1 = -INFINITY;
        #pragma unroll
        for (int e = 0; e < NE; e++) if (e != e0 && v[e] > b1) { b1 = v[e]; e1 = e; }
        float ex  = expf(b1 - b0);
        float inv = 1.f / (1.f + ex);
        atomicAdd(&g_counts[e0], 1);
        atomicAdd(&g_counts[e1], 1);
        g_tok_e[2*t]   = e0;      g_tok_e[2*t+1] = e1;
        g_tok_g[2*t]   = inv;     g_tok_g[2*t+1] = ex * inv;
    }
}

__global__ void offsets_kernel() {
    if (threadIdx.x == 0) {
        int off = 0;
        for (int e = 0; e < NE; e++) {
            g_offsets[e] = off;
            int p = ((g_counts[e] + BM - 1) / BM) * BM;
            g_padded[e] = p;
            off += p;
        }
    }
}

__global__ void clear_rows_kernel() {
    int i = blockIdx.x * blockDim.x + threadIdx.x;
    if (i < MAXROWS) g_row_token[i] = -1;
}

__global__ void scatter_kernel() {
    int i = blockIdx.x * blockDim.x + threadIdx.x;
    if (i < 2*NT) {
        int e   = g_tok_e[i];
        int pos = atomicAdd(&g_fill[e], 1);
        int row = g_offsets[e] + pos;
        g_row_token[row] = i >> 1;
        g_tok_row[i]     = row;
    }
}

/* ---------------- TF32 MMA helpers ---------------- */

__device__ __forceinline__ uint32_t f2tf32(float f) {
    uint32_t u; asm("cvt.rna.tf32.f32 %0, %1;" : "=r"(u) : "f"(f)); return u;
}

__device__ __forceinline__ void ldsm_x4(uint32_t* r, uint32_t saddr) {
    asm volatile("ldmatrix.sync.aligned.m8n8.x4.shared.b16 {%0,%1,%2,%3}, [%4];"
                 : "=r"(r[0]), "=r"(r[1]), "=r"(r[2]), "=r"(r[3]) : "r"(saddr));
}

__device__ __forceinline__ void mma_tf32(float* d, const uint32_t* a, const uint32_t* b) {
    asm volatile("mma.sync.aligned.m16n8k8.row.col.f32.tf32.tf32.f32 "
                 "{%0,%1,%2,%3},{%4,%5,%6,%7},{%8,%9},{%0,%1,%2,%3};"
                 : "+f"(d[0]), "+f"(d[1]), "+f"(d[2]), "+f"(d[3])
                 : "r"(a[0]), "r"(a[1]), "r"(a[2]), "r"(a[3]), "r"(b[0]), "r"(b[1]));
}

/* ---------------- fused gather-GEMM (TF32), 128x128x32 tile ----------------
   GELU=true : Out=g_H = gelu(gather(x) @ W1[e] + b1),  KD=768,  ND=3072
   GELU=false: Out=g_Y = g_H @ W2[e] + b2,              KD=3072, ND=768     */

template<int KD, int ND, bool GELU>
__global__ __launch_bounds__(256, 1)
void mma_gemm_kernel(const float* __restrict__ Asrc,
                     const float* __restrict__ W,
                     const float* __restrict__ bias)
{
    extern __shared__ float smem[];
    int e  = blockIdx.y >> 7;
    int tj = blockIdx.y & 127;
    if (tj * BM >= g_padded[e]) return;
    int row0 = g_offsets[e] + tj * BM;
    int col0 = blockIdx.x * BN;

    int tid  = threadIdx.x;
    int lane = tid & 31;
    int wid  = tid >> 5;
    int wm   = wid & 1;        /* 2 warp rows  -> 64 rows  */
    int wn   = wid >> 1;       /* 4 warp cols  -> 32 cols  */
    int m_base = wm * 64;
    int n_base = wn * 32;

    int* s_tok = (int*)(smem + 2*ABUF + 2*BBUF);
    if (tid < BM) s_tok[tid] = g_row_token[row0 + tid];
    __syncthreads();

    const float* Wsrc = W + (size_t)e * KD * ND;

    /* staging pointers: A 128x32 (4 float4/thread), B 32x128 (4 float4/thread) */
    const float* aptr[4];
    int a_soff[4];
    #pragma unroll
    for (int it = 0; it < 4; it++) {
        int idx = tid + it * 256;
        int r   = idx >> 3;
        int kq  = idx & 7;
        a_soff[it] = r * AS_STRIDE + kq * 4;
        if (GELU) {
            int tok = s_tok[r];
            aptr[it] = (tok >= 0) ? (Asrc + (size_t)tok * KD + kq * 4) : (const float*)0;
        } else {
            aptr[it] = g_H + (size_t)(row0 + r) * KD + kq * 4;
        }
    }
    const float* bptr[4];
    int b_soff[4];
    #pragma unroll
    for (int it = 0; it < 4; it++) {
        int idx = tid + it * 256;
        int kr  = idx >> 5;
        int nq  = idx & 31;
        b_soff[it] = kr * BS_STRIDE + nq * 4;
        bptr[it] = Wsrc + (size_t)kr * ND + col0 + nq * 4;
    }

    uint32_t smem_u32 = (uint32_t)__cvta_generic_to_shared(smem);
    /* ldmatrix lane address: row = lane&15, k-offset = 4*(lane>>4) */
    int a_lane_off = ((m_base + (lane & 15)) * AS_STRIDE + 4 * (lane >> 4)) * 4;

    float acc[4][4][4];
    #pragma unroll
    for (int i = 0; i < 4; i++)
        #pragma unroll
        for (int j = 0; j < 4; j++)
            #pragma unroll
            for (int c = 0; c < 4; c++) acc[i][j][c] = 0.f;

    float4 va[4], vb[4];
    const float4 z4 = make_float4(0.f,0.f,0.f,0.f);

    /* prologue: load k-tile 0 */
    #pragma unroll
    for (int it = 0; it < 4; it++) {
        va[it] = aptr[it] ? *(const float4*)(aptr[it]) : z4;
        vb[it] = *(const float4*)(bptr[it]);
    }
    #pragma unroll
    for (int it = 0; it < 4; it++) {
        float* as = smem + a_soff[it];
        as[0] = __uint_as_float(f2tf32(va[it].x));
        as[1] = __uint_as_float(f2tf32(va[it].y));
        as[2] = __uint_as_float(f2tf32(va[it].z));
        as[3] = __uint_as_float(f2tf32(va[it].w));
        float* bs = smem + 2*ABUF + b_soff[it];
        bs[0] = __uint_as_float(f2tf32(vb[it].x));
        bs[1] = __uint_as_float(f2tf32(vb[it].y));
        bs[2] = __uint_as_float(f2tf32(vb[it].z));
        bs[3] = __uint_as_float(f2tf32(vb[it].w));
    }
    __syncthreads();

    const int NK = KD / BK;
    int buf = 0;
    for (int kt = 0; kt < NK; kt++) {
        bool has_next = (kt + 1) < NK;
        if (has_next) {
            int k0 = (kt + 1) * BK;
            #pragma unroll
            for (int it = 0; it < 4; it++) {
                va[it] = aptr[it] ? *(const float4*)(aptr[it] + k0) : z4;
                vb[it] = *(const float4*)(bptr[it] + (size_t)k0 * ND);
            }
        }
        /* compute on buf */
        {
            const float* Bsf = smem + 2*ABUF + buf * BBUF;
            uint32_t As_u = smem_u32 + (buf * ABUF) * 4 + a_lane_off;
            #pragma unroll
            for (int kk8 = 0; kk8 < 4; kk8++) {
                int kk = kk8 * 8;
                uint32_t a[4][4];
                #pragma unroll
                for (int mi = 0; mi < 4; mi++)
                    ldsm_x4(a[mi], As_u + (mi * 16 * AS_STRIDE + kk) * 4);
                uint32_t b[4][2];
                #pragma unroll
                for (int ni = 0; ni < 4; ni++) {
                    int n = n_base + ni * 8 + (lane >> 2);
                    b[ni][0] = __float_as_uint(Bsf[(kk + (lane & 3)) * BS_STRIDE + n]);
                    b[ni][1] = __float_as_uint(Bsf[(kk + (lane & 3) + 4) * BS_STRIDE + n]);
                }
                #pragma unroll
                for (int mi = 0; mi < 4; mi++)
                    #pragma unroll
                    for (int ni = 0; ni < 4; ni++)
                        mma_tf32(acc[mi][ni], a[mi], b[ni]);
            }
        }
        if (has_next) {
            int nb = buf ^ 1;
            #pragma unroll
            for (int it = 0; it < 4; it++) {
                float* as = smem + nb * ABUF + a_soff[it];
                as[0] = __uint_as_float(f2tf32(va[it].x));
                as[1] = __uint_as_float(f2tf32(va[it].y));
                as[2] = __uint_as_float(f2tf32(va[it].z));
                as[3] = __uint_as_float(f2tf32(va[it].w));
                float* bs = smem + 2*ABUF + nb * BBUF + b_soff[it];
                bs[0] = __uint_as_float(f2tf32(vb[it].x));
                bs[1] = __uint_as_float(f2tf32(vb[it].y));
                bs[2] = __uint_as_float(f2tf32(vb[it].z));
                bs[3] = __uint_as_float(f2tf32(vb[it].w));
            }
            __syncthreads();
            buf = nb;
        }
    }

    /* epilogue */
    float* Outp = GELU ? g_H : g_Y;
    int gid = lane >> 2;
    int tig = lane & 3;
    #pragma unroll
    for (int mi = 0; mi < 4; mi++) {
        #pragma unroll
        for (int part = 0; part < 2; part++) {
            int m = m_base + mi * 16 + gid + part * 8;
            int tok = s_tok[m];
            if (tok < 0) continue;
            float* dst = Outp + (size_t)(row0 + m) * ND + col0;
            #pragma unroll
            for (int ni = 0; ni < 4; ni++) {
                int c = n_base + ni * 8 + tig * 2;
                float v0 = acc[mi][ni][part*2+0] + bias[e * ND + col0 + c];
                float v1 = acc[mi][ni][part*2+1] + bias[e * ND + col0 + c + 1];
                if (GELU) {
                    v0 = 0.5f * v0 * (1.f + erff(v0 * 0.70710678118654752f));
                    v1 = 0.5f * v1 * (1.f + erff(v1 * 0.70710678118654752f));
                }
                *(float2*)(dst + c) = make_float2(v0, v1);
            }
        }
    }
}

/* ---------------- combine ---------------- */

__global__ void combine_kernel(float* __restrict__ out) {
    int idx = blockIdx.x * blockDim.x + threadIdx.x;
    if (idx >= NT * DIMV) return;
    int t = idx / DIMV;
    int d = idx - t * DIMV;
    int   r0 = g_tok_row[2*t],   r1 = g_tok_row[2*t+1];
    float g0 = g_tok_g[2*t],     g1 = g_tok_g[2*t+1];
    float acc = g0 * expf(g_Y[(size_t)r0 * DIMV + d])
              + g1 * expf(g_Y[(size_t)r1 * DIMV + d]);
    out[idx] = logf(acc == 0.f ? 2.2204460492503131e-16f : acc);
}

/* ---------------- launch ---------------- */

extern "C" void kernel_launch(void* const* d_in, const int* in_sizes, int n_in,
                              void* d_out, int out_size) {
    (void)in_sizes; (void)n_in; (void)out_size;
    const float* x   = (const float*)d_in[0];
    const float* wg  = (const float*)d_in[1];
    const float* W1  = (const float*)d_in[2];
    const float* b1v = (const float*)d_in[3];
    const float* W2  = (const float*)d_in[4];
    const float* b2v = (const float*)d_in[5];
    float* out = (float*)d_out;

    cudaFuncSetAttribute(mma_gemm_kernel<DIMV, HIDV, true>,
                         cudaFuncAttributeMaxDynamicSharedMemorySize, SMEM_BYTES);
    cudaFuncSetAttribute(mma_gemm_kernel<HIDV, DIMV, false>,
                         cudaFuncAttributeMaxDynamicSharedMemorySize, SMEM_BYTES);

    zero_kernel<<<1, 32>>>();
    gate_kernel<<<NT/4, 128>>>(x, wg);
    offsets_kernel<<<1, 32>>>();
    clear_rows_kernel<<<(MAXROWS + 255)/256, 256>>>();
    scatter_kernel<<<(2*NT + 255)/256, 256>>>();

    dim3 g1(HIDV / BN, NE * (NT / BM));
    mma_gemm_kernel<DIMV, HIDV, true><<<g1, 256, SMEM_BYTES>>>(x, W1, b1v);

    dim3 g2(DIMV / BN, NE * (NT / BM));
    mma_gemm_kernel<HIDV, DIMV, false><<<g2, 256, SMEM_BYTES>>>(x, W2, b2v);

    combine_kernel<<<(NT*DIMV + 255)/256, 256>>>(out);
}